// round 7
// baseline (speedup 1.0000x reference)
#include <cuda_runtime.h>
#include <cstdint>

typedef unsigned long long ull;

// Problem constants
#define NB 8
#define NW 32
#define NX 64
#define NY 64
#define NT 40
#define NKZ 8          // retained T modes (M3)
#define NK 24          // retained X/Y modes (2*M1 = 2*M2)
#define XYT 163840     // 64*64*40
#define YTD 2560       // 64*40
#define NMODE 4608     // 24*24*8
#define WPL 4718592    // 4*32*32*12*12*8  (spectral weights per layer)

// ---- scratch (device globals; no allocations anywhere) ----
static __device__ float  g_bufA[(size_t)NB*NW*XYT];                 // 168 MB
static __device__ float  g_bufB[(size_t)NB*NW*XYT];                 // 168 MB
static __device__ float2 g_ft1[(size_t)NB*NW*NX*NY*NKZ];            // 67 MB
static __device__ float2 g_ft2[(size_t)NB*NW*NX*NK*NKZ];            // 25 MB
static __device__ float2 g_modes [(size_t)NB*NW*NMODE];             // 9.4 MB
static __device__ float2 g_modes2[(size_t)NB*NW*NMODE];             // 9.4 MB
static __device__ float2 g_wt[(size_t)3*WPL];                       // 113 MB
static __device__ float2 g_tw_t[NKZ*NT];    // forward T twiddles  e^{-2pi i k t/40}
static __device__ float2 g_tw_yx[NK*64];    // forward X/Y twiddles e^{-2pi i kv y/64}
static __device__ ull    g_itw2x[NKZ*20];   // packed inverse-T cos pairs: [k][tpair]
static __device__ ull    g_itw2y[NKZ*20];   // packed inverse-T sin pairs: [k][tpair]

// ---- f32x2 helpers ----
__device__ __forceinline__ ull pack2(float lo, float hi){
  ull r; asm("mov.b64 %0, {%1, %2};" : "=l"(r) : "f"(lo), "f"(hi)); return r;
}
__device__ __forceinline__ ull dup2(float x){ return pack2(x, x); }
__device__ __forceinline__ void unpack2(ull v, float& lo, float& hi){
  asm("mov.b64 {%0, %1}, %2;" : "=f"(lo), "=f"(hi) : "l"(v));
}
__device__ __forceinline__ ull fma2(ull a, ull b, ull c){
  ull d; asm("fma.rn.f32x2 %0, %1, %2, %3;" : "=l"(d) : "l"(a), "l"(b), "l"(c)); return d;
}

__device__ __forceinline__ void cfma(float2& a, float2 b, float2 c){
  a.x = fmaf(b.x, c.x, fmaf(-b.y, c.y, a.x));
  a.y = fmaf(b.x, c.y, fmaf( b.y, c.x, a.y));
}
__device__ __forceinline__ void cfma_cj(float2& a, float2 b, float2 c){ // a += b*conj(c)
  a.x = fmaf(b.x, c.x, fmaf( b.y, c.y, a.x));
  a.y = fmaf(b.y, c.x, fmaf(-b.x, c.y, a.y));
}
__device__ __forceinline__ float gelu_f(float z){
  return 0.5f*z*(1.0f + erff(z*0.7071067811865476f));
}

// ---- twiddle tables ----
__global__ void k_init_tw(){
  int tid = threadIdx.x;
  for (int i = tid; i < NKZ*NT; i += blockDim.x){
    int k = i / NT, t = i % NT;
    float s, c; sincospif(-(float)(k*t)/20.0f, &s, &c);   // -2pi k t / 40
    g_tw_t[i] = make_float2(c, s);
  }
  for (int i = tid; i < NKZ*20; i += blockDim.x){
    int k = i / 20, p = i % 20;
    float sc = ((k==0) ? 1.0f : 2.0f) * (1.0f/163840.0f);
    float s0, c0, s1, c1;
    sincospif((float)(k*(2*p  ))/20.0f, &s0, &c0);
    sincospif((float)(k*(2*p+1))/20.0f, &s1, &c1);
    g_itw2x[i] = pack2(sc*c0, sc*c1);
    g_itw2y[i] = pack2(sc*s0, sc*s1);
  }
  for (int i = tid; i < NK*64; i += blockDim.x){
    int j = i / 64, y = i % 64;
    int kv = (j < 12) ? j : j + 40;                        // 0..11, 52..63
    float s, c; sincospif(-(float)(kv*y)/32.0f, &s, &c);   // -2pi kv y / 64
    g_tw_yx[i] = make_float2(c, s);
  }
}

// ---- transpose spectral weights via 32x32 shared tile ----
__global__ void __launch_bounds__(256) k_prep_w_t(const float* __restrict__ wr,
                                                  const float* __restrict__ wi, int L){
  __shared__ float2 s[32][33];
  int m0  = blockIdx.x * 32;
  int io0 = blockIdx.y * 32;
  int r   = blockIdx.z;
  int tid = threadIdx.x;
  {
    int mt = tid & 31, iot0 = tid >> 5;
    const size_t inbase = (size_t)r * 1024 * 1152;
    #pragma unroll
    for (int u = 0; u < 4; u++){
      int io = io0 + iot0 + u*8;
      size_t off = inbase + (size_t)io*1152 + m0 + mt;
      s[iot0 + u*8][mt] = make_float2(wr[off], wi[off]);
    }
  }
  __syncthreads();
  {
    int iot = tid & 31, mt0 = tid >> 5;
    int rbase = (r & 1) * 2304 + ((r >> 1) & 1) * 96;
    float2* dst = g_wt + (size_t)L*WPL;
    #pragma unroll
    for (int u = 0; u < 4; u++){
      int m  = m0 + mt0 + u*8;
      int m1 = m / 96, rem = m % 96;
      int mode = rbase + m1*192 + rem;
      dst[(size_t)mode*1024 + io0 + iot] = s[iot][mt0 + u*8];
    }
  }
}

// ---- fc0: lift [B,X,Y,T,5] -> v [B,W,X,Y,T] ----
__global__ void k_fc0(const float* __restrict__ h, const float* __restrict__ xin,
                      const float* __restrict__ w, const float* __restrict__ b){
  int p = blockIdx.x * blockDim.x + threadIdx.x;
  if (p >= NB*XYT) return;
  int bb = p / XYT, rem = p % XYT;
  float in5[5];
  in5[0] = h[(size_t)p*2];   in5[1] = h[(size_t)p*2+1];
  in5[2] = xin[(size_t)p*3]; in5[3] = xin[(size_t)p*3+1]; in5[4] = xin[(size_t)p*3+2];
  float* o = g_bufA + (size_t)bb*NW*XYT + rem;
  #pragma unroll 4
  for (int c = 0; c < NW; c++){
    float v = b[c];
    #pragma unroll
    for (int f = 0; f < 5; f++) v = fmaf(in5[f], w[f*NW + c], v);
    o[(size_t)c*XYT] = v;
  }
}

// ---- forward partial DFT over T (f32x2, 2 x-slices per block) ----
__global__ void __launch_bounds__(64) k_fwdT2(int dir){
  __shared__ float s[2][NY*41];
  __shared__ ull   stw[NT*NKZ];     // [t][k] packed (re,im)
  const float* vin = dir ? g_bufB : g_bufA;
  int bcx0 = blockIdx.x * 2;
  const float* src = vin + (size_t)bcx0*YTD;
  int tid = threadIdx.x;
  for (int i = tid; i < 2*YTD; i += 64){
    int sl = i / YTD, r = i % YTD;
    s[sl][(r/NT)*41 + (r%NT)] = src[i];
  }
  for (int i = tid; i < NT*NKZ; i += 64){
    int k = i / NT, t = i % NT;
    stw[t*NKZ + k] = ((const ull*)g_tw_t)[k*NT + t];
  }
  __syncthreads();
  int y = tid;
  ull acc0[NKZ], acc1[NKZ];
  #pragma unroll
  for (int k = 0; k < NKZ; k++){ acc0[k] = 0ull; acc1[k] = 0ull; }
  for (int t = 0; t < NT; t++){
    ull v0 = dup2(s[0][y*41 + t]);
    ull v1 = dup2(s[1][y*41 + t]);
    const ull* twp = stw + t*NKZ;
    #pragma unroll
    for (int k = 0; k < NKZ; k++){
      ull tw = twp[k];
      acc0[k] = fma2(v0, tw, acc0[k]);
      acc1[k] = fma2(v1, tw, acc1[k]);
    }
  }
  ull* d0 = (ull*)(g_ft1 + ((size_t)bcx0*NY + y)*NKZ);
  ull* d1 = (ull*)(g_ft1 + ((size_t)(bcx0+1)*NY + y)*NKZ);
  #pragma unroll
  for (int k = 0; k < NKZ; k++){ d0[k] = acc0[k]; d1[k] = acc1[k]; }
}

// ---- forward partial DFT over Y ----
__global__ void k_fwdY(){
  __shared__ float2 sv[NY*NKZ];
  __shared__ float2 stw[NK*64];
  int bcx = blockIdx.x;
  for (int i = threadIdx.x; i < NY*NKZ; i += 192) sv[i] = g_ft1[(size_t)bcx*512 + i];
  for (int i = threadIdx.x; i < NK*64; i += 192) stw[i] = g_tw_yx[i];
  __syncthreads();
  int j = threadIdx.x >> 3, k = threadIdx.x & 7;
  float2 acc = make_float2(0.f, 0.f);
  for (int y = 0; y < 64; y++) cfma(acc, sv[y*8 + k], stw[j*64 + y]);
  g_ft2[(size_t)bcx*192 + threadIdx.x] = acc;
}

// ---- forward partial DFT over X ----
__global__ void k_fwdX(){
  __shared__ float2 stw[64];
  int bc = blockIdx.x / NK, j1 = blockIdx.x % NK;
  if (threadIdx.x < 64) stw[threadIdx.x] = g_tw_yx[j1*64 + threadIdx.x];
  __syncthreads();
  const float2* src = g_ft2 + (size_t)bc*NX*192 + threadIdx.x;
  float2 acc = make_float2(0.f, 0.f);
  for (int x = 0; x < 64; x++) cfma(acc, src[(size_t)x*192], stw[x]);
  g_modes[(size_t)bc*NMODE + j1*192 + threadIdx.x] = acc;
}

// ---- channel mix per mode ----
__global__ void k_mix(int L){
  __shared__ float2 s_in[256];
  __shared__ float2 s_w[1024];
  int m = blockIdx.x;
  int tid = threadIdx.x;
  s_in[tid] = g_modes[(size_t)tid*NMODE + m];
  const float2* wt = g_wt + (size_t)L*WPL + (size_t)m*1024;
  for (int i = tid; i < 1024; i += 256) s_w[i] = wt[i];
  __syncthreads();
  int bb = tid >> 5, o = tid & 31;
  float2 acc = make_float2(0.f, 0.f);
  #pragma unroll 8
  for (int i = 0; i < 32; i++) cfma(acc, s_in[bb*32 + i], s_w[i*32 + o]);
  g_modes2[(size_t)(bb*32 + o)*NMODE + m] = acc;
}

// ---- inverse over X ----
__global__ void k_invX(){
  __shared__ float2 stw[NK*64];
  int bo = blockIdx.x;
  int tid = threadIdx.x;
  for (int i = tid; i < NK*64; i += 192) stw[i] = g_tw_yx[i];
  float2 m[NK];
  #pragma unroll
  for (int j1 = 0; j1 < NK; j1++)
    m[j1] = g_modes2[(size_t)bo*NMODE + j1*192 + tid];
  __syncthreads();
  for (int x = 0; x < 64; x++){
    float2 acc = make_float2(0.f, 0.f);
    #pragma unroll
    for (int j1 = 0; j1 < NK; j1++) cfma_cj(acc, m[j1], stw[j1*64 + x]);
    g_ft2[((size_t)bo*64 + x)*192 + tid] = acc;
  }
}

// ---- inverse over Y ----
__global__ void k_invY(){
  __shared__ float2 s_in[192];
  __shared__ float2 stw[NK*64];
  int box = blockIdx.x;
  if (threadIdx.x < 192) s_in[threadIdx.x] = g_ft2[(size_t)box*192 + threadIdx.x];
  for (int i = threadIdx.x; i < NK*64; i += 256) stw[i] = g_tw_yx[i];
  __syncthreads();
  for (int o = threadIdx.x; o < 512; o += 256){
    int y = o >> 3, k = o & 7;
    float2 acc = make_float2(0.f, 0.f);
    #pragma unroll 8
    for (int j2 = 0; j2 < NK; j2++) cfma_cj(acc, s_in[j2*8 + k], stw[j2*64 + y]);
    g_ft1[(size_t)box*512 + o] = acc;
  }
}

// ---- inverse over T + conv1x1 + bias + optional gelu (f32x2, 4 xy per block) ----
// Thread tile: 2 o x 8 t (4 packed t-pairs).
__global__ void __launch_bounds__(320) k_invT_pw2(int dir, const float* __restrict__ convw,
                          const float* __restrict__ convb, int act){
  __shared__ __align__(16) float s_v[4*1280];   // [q][c][t]
  __shared__ float2 s_wd[1024];                  // dup-packed conv w: [o*32+i] = {w,w}
  __shared__ float2 s_h[4*288];                  // [q][o*9+k]
  __shared__ ull   s_ix[NKZ*20];                 // packed itw cos
  __shared__ ull   s_iy[NKZ*20];                 // packed itw sin
  __shared__ float s_b[NW];
  const float* vin  = dir ? g_bufB : g_bufA;
  float*       vout = dir ? g_bufA : g_bufB;
  int gx  = blockIdx.x;
  int bb  = gx >> 10;                // 1024 groups of 4 xy per batch
  int xy0 = (gx & 1023) * 4;
  int tid = threadIdx.x;
  size_t base = (size_t)(bb*32)*XYT + (size_t)xy0*NT;

  // load v: 32 c x 160 floats (4 xy * 40 t, contiguous) = 40 float4 per c
  for (int idx = tid; idx < 1280; idx += 320){
    int c = idx / 40, m = idx % 40;
    float4 v4 = *(const float4*)(vin + base + (size_t)c*XYT + m*4);
    int q = m / 10, mm = m % 10;
    *(float4*)&s_v[q*1280 + c*40 + mm*4] = v4;
  }
  // spectral coefficients for 4 xy
  for (int idx = tid; idx < 1024; idx += 320){
    int q = idx >> 8, rem = idx & 255, o = rem >> 3, k = rem & 7;
    s_h[q*288 + o*9 + k] = g_ft1[(size_t)(bb*32+o)*32768 + (size_t)(xy0+q)*8 + k];
  }
  for (int i = tid; i < 1024; i += 320){
    float w = convw[i];
    s_wd[i] = make_float2(w, w);     // convw is [o][i] row-major
  }
  for (int i = tid; i < NKZ*20; i += 320){ s_ix[i] = g_itw2x[i]; s_iy[i] = g_itw2y[i]; }
  if (tid < NW) s_b[tid] = convb[tid];
  __syncthreads();

  int q  = tid / 80, r = tid % 80;
  int o0 = (r / 5) * 2;              // 16 o-pairs
  int t0 = (r % 5) * 8;              // 5 t-groups of 8
  ull a0[4], a1[4];
  {
    ull b0 = dup2(s_b[o0]), b1 = dup2(s_b[o0+1]);
    #pragma unroll
    for (int p = 0; p < 4; p++){ a0[p] = b0; a1[p] = b1; }
  }
  // idft-T: acc += hx*cos - hy*sin   (packed over t pairs)
  {
    const float2* hp0 = s_h + q*288 + o0*9;
    const float2* hp1 = hp0 + 9;
    int pb = t0 >> 1;                // pair base
    #pragma unroll
    for (int k = 0; k < NKZ; k++){
      float2 h0 = hp0[k], h1 = hp1[k];
      ull d0x = dup2(h0.x), d0y = dup2(-h0.y);
      ull d1x = dup2(h1.x), d1y = dup2(-h1.y);
      const ull* cx = s_ix + k*20 + pb;
      const ull* sy = s_iy + k*20 + pb;
      #pragma unroll
      for (int p = 0; p < 4; p++){
        ull c = cx[p], sn = sy[p];
        a0[p] = fma2(d0x, c, fma2(d0y, sn, a0[p]));
        a1[p] = fma2(d1x, c, fma2(d1y, sn, a1[p]));
      }
    }
  }
  // conv1x1 (packed over t pairs, dup-packed weights)
  {
    const float* vh = s_v + q*1280;
    const ull* wd0 = (const ull*)(s_wd + o0*32);
    const ull* wd1 = (const ull*)(s_wd + (o0+1)*32);
    #pragma unroll 8
    for (int i = 0; i < 32; i++){
      ull w0 = wd0[i], w1 = wd1[i];
      const ull* vp = (const ull*)(vh + i*40 + t0);
      #pragma unroll
      for (int p = 0; p < 4; p++){
        ull vv = vp[p];
        a0[p] = fma2(w0, vv, a0[p]);
        a1[p] = fma2(w1, vv, a1[p]);
      }
    }
  }
  __syncthreads();                   // all reads of s_v done
  {
    ull* ov0 = (ull*)(s_v + q*1280 + o0*40 + t0);
    ull* ov1 = (ull*)(s_v + q*1280 + (o0+1)*40 + t0);
    #pragma unroll
    for (int p = 0; p < 4; p++){
      float z0, z1, y0, y1;
      unpack2(a0[p], z0, z1);
      unpack2(a1[p], y0, y1);
      if (act){ z0 = gelu_f(z0); z1 = gelu_f(z1); y0 = gelu_f(y0); y1 = gelu_f(y1); }
      ov0[p] = pack2(z0, z1);
      ov1[p] = pack2(y0, y1);
    }
  }
  __syncthreads();
  // coalesced float4 writeback
  for (int idx = tid; idx < 1280; idx += 320){
    int c = idx / 40, m = idx % 40;
    int q2 = m / 10, mm = m % 10;
    float4 v4 = *(const float4*)&s_v[q2*1280 + c*40 + mm*4];
    *(float4*)(vout + base + (size_t)c*XYT + m*4) = v4;
  }
}

// ---- head: fc1 (gelu) + fc2 with f32x2 over t-pairs and dup-packed w1 ----
__global__ void __launch_bounds__(256) k_head(const float* __restrict__ w1, const float* __restrict__ b1,
                       const float* __restrict__ w2, const float* __restrict__ b2,
                       float* __restrict__ out){
  __shared__ __align__(16) float2 s_w1d[2048];  // [c*64+j] = {w,w}
  __shared__ float s_b1[64];
  __shared__ float s_w2[128];
  __shared__ float s_b2[2];
  int tid = threadIdx.x;
  for (int i = tid; i < 2048; i += 256){
    float w = w1[i];
    s_w1d[i] = make_float2(w, w);
  }
  if (tid < 64)  s_b1[tid] = b1[tid];
  if (tid < 128) s_w2[tid] = w2[tid];
  if (tid < 2)   s_b2[tid] = b2[tid];
  __syncthreads();
  if (tid >= 240) return;
  int xy_l = tid / 20, tp = tid % 20;        // thread covers t=2*tp, 2*tp+1
  int g = blockIdx.x * 12 + xy_l;
  if (g >= 32768) return;
  int bb = g >> 12, xy = g & 4095;
  ull vreg[32];
  const float* vb = g_bufB + (size_t)(bb*32)*XYT + (size_t)xy*NT + tp*2;
  #pragma unroll
  for (int c = 0; c < 32; c++) vreg[c] = *(const ull*)(vb + (size_t)c*XYT);
  ull oc0 = pack2(s_b2[0], s_b2[1]);         // out-chan pair for t
  ull oc1 = oc0;                             // for t+1
  const ull* w2p = (const ull*)s_w2;
  for (int j = 0; j < 64; j += 2){
    ull h0 = dup2(s_b1[j]);
    ull h1 = dup2(s_b1[j+1]);
    #pragma unroll 8
    for (int c = 0; c < 32; c++){
      ulonglong2 wq = *(const ulonglong2*)(s_w1d + c*64 + j);
      ull v = vreg[c];
      h0 = fma2(v, wq.x, h0);
      h1 = fma2(v, wq.y, h1);
    }
    float h0a, h0b, h1a, h1b;
    unpack2(h0, h0a, h0b);
    unpack2(h1, h1a, h1b);
    float g0a = gelu_f(h0a), g0b = gelu_f(h0b);
    float g1a = gelu_f(h1a), g1b = gelu_f(h1b);
    ull wj0 = w2p[j], wj1 = w2p[j+1];
    oc0 = fma2(dup2(g0a), wj0, oc0);
    oc1 = fma2(dup2(g0b), wj0, oc1);
    oc0 = fma2(dup2(g1a), wj1, oc0);
    oc1 = fma2(dup2(g1b), wj1, oc1);
  }
  float o00, o01, o10, o11;
  unpack2(oc0, o00, o01);
  unpack2(oc1, o10, o11);
  float4 res = make_float4(o00, o01, o10, o11);
  *(float4*)(out + (size_t)g*80 + tp*4) = res;
}

static void run_layer(int L, int dir, int act, const float* convw, const float* convb){
  k_fwdT2<<<NB*NW*NX/2, 64>>>(dir);
  k_fwdY<<<NB*NW*NX, 192>>>();
  k_fwdX<<<NB*NW*NK, 192>>>();
  k_mix<<<NMODE, 256>>>(L);
  k_invX<<<NB*NW, 192>>>();
  k_invY<<<NB*NW*NX, 256>>>();
  k_invT_pw2<<<NB*1024, 320>>>(dir, convw, convb, act);
}

extern "C" void kernel_launch(void* const* d_in, const int* in_sizes, int n_in,
                              void* d_out, int out_size){
  (void)in_sizes; (void)n_in; (void)out_size;
  const float* h     = (const float*)d_in[0];
  const float* xin   = (const float*)d_in[1];
  const float* fc0_w = (const float*)d_in[2];
  const float* fc0_b = (const float*)d_in[3];
  const float* scr[3] = {(const float*)d_in[4], (const float*)d_in[6], (const float*)d_in[8]};
  const float* sci[3] = {(const float*)d_in[5], (const float*)d_in[7], (const float*)d_in[9]};
  const float* cw[3]  = {(const float*)d_in[10], (const float*)d_in[12], (const float*)d_in[14]};
  const float* cb[3]  = {(const float*)d_in[11], (const float*)d_in[13], (const float*)d_in[15]};
  const float* fc1_w = (const float*)d_in[16];
  const float* fc1_b = (const float*)d_in[17];
  const float* fc2_w = (const float*)d_in[18];
  const float* fc2_b = (const float*)d_in[19];
  float* out = (float*)d_out;

  k_init_tw<<<1, 256>>>();
  dim3 pgrid(36, 32, 4);
  for (int L = 0; L < 3; L++)
    k_prep_w_t<<<pgrid, 256>>>(scr[L], sci[L], L);
  k_fc0<<<(NB*XYT)/256, 256>>>(h, xin, fc0_w, fc0_b);

  run_layer(0, 0, 1, cw[0], cb[0]);   // A -> B, gelu
  run_layer(1, 1, 1, cw[1], cb[1]);   // B -> A, gelu
  run_layer(2, 0, 0, cw[2], cb[2]);   // A -> B, no act

  k_head<<<(32768 + 11)/12, 256>>>(fc1_w, fc1_b, fc2_w, fc2_b, out);
}